// round 9
// baseline (speedup 1.0000x reference)
#include <cuda_runtime.h>

#define GN     128
#define GMASK  127
#define NCELLS (GN * GN * GN)

// grid scratch: [cell][2 float4] = 64 MB, plain z-major
__device__ float4 g_grid[NCELLS * 2];

// ---------------- P2G: 16 lanes/point, 2 points/warp (at REDG lane-op floor ~63us) --------
__global__ __launch_bounds__(256)
void p2g_coop(const float* __restrict__ pos,
              const float4* __restrict__ feat4, int n) {
    int lane = threadIdx.x & 31;
    int warp = (blockIdx.x * blockDim.x + threadIdx.x) >> 5;
    int i = warp * 2 + (lane >> 4);
    if (i >= n) return;

    int k = lane & 15;
    int node = k >> 1;
    int half = k & 1;
    int ox = node >> 2, oy = (node >> 1) & 1, oz = node & 1;

    float rx = __ldg(&pos[3 * i + 0]) * (float)GN;
    float ry = __ldg(&pos[3 * i + 1]) * (float)GN;
    float rz = __ldg(&pos[3 * i + 2]) * (float)GN;
    int bx = (int)rx, by = (int)ry, bz = (int)rz;
    float fx = rx - (float)bx, fy = ry - (float)by, fz = rz - (float)bz;

    float w = (ox ? fx : 1.0f - fx) * (oy ? fy : 1.0f - fy) * (oz ? fz : 1.0f - fz);

    float4 f = __ldg(&feat4[2 * i + half]);

    int nx = (bx + ox) & GMASK;     // only the +1 offsets can wrap
    int ny = (by + oy) & GMASK;
    int nz = (bz + oz) & GMASK;
    int nid = ((nx << 7 | ny) << 7) | nz;

    float4 c = make_float4(w * f.x, w * f.y, w * f.z, w * f.w);
    atomicAdd(&g_grid[2 * nid + half], c);
}

// ---------------- G2P: 8 lanes/point, 4 points/THREAD (16 pts/warp) ----------------
// lane = p*8 + s;  s: oy=bit2, oz=bit1, half=bit0.  Thread handles points
// i_m = warp*16 + p + 4*m, m=0..3.  8 independent grid LDG.128 in flight.
// ox summed in registers; butterfly reduces oz (xor2) then oy (xor4), 3 SHFL/pt.
// Final: lane holds comp = half*4+oz*2+oy per point; 4 coalesced 128B stores/warp.
struct PtCtx { float wA, wB; int nidA, nidB; };

__device__ __forceinline__ PtCtx g2p_setup(const float* __restrict__ pos, int i,
                                           int oy, int oz) {
    float rx = __ldg(&pos[3 * i + 0]) * (float)GN;
    float ry = __ldg(&pos[3 * i + 1]) * (float)GN;
    float rz = __ldg(&pos[3 * i + 2]) * (float)GN;
    int bx = (int)rx, by = (int)ry, bz = (int)rz;
    float fx = rx - (float)bx, fy = ry - (float)by, fz = rz - (float)bz;

    float wyz = (oy ? fy : 1.0f - fy) * (oz ? fz : 1.0f - fz);
    PtCtx c;
    c.wA = (1.0f - fx) * wyz;
    c.wB = fx * wyz;
    int ny = (by + oy) & GMASK;
    int nz = (bz + oz) & GMASK;
    c.nidA = ((bx << 7 | ny) << 7) | nz;                  // bx in [0,127]: no mask
    c.nidB = ((((bx + 1) & GMASK) << 7 | ny) << 7) | nz;
    return c;
}

__device__ __forceinline__ float g2p_reduce(float v0, float v1, float v2, float v3,
                                            bool soz, bool soy) {
    float t, r, a0, a1;
    t = soz ? v0 : v2;  r = __shfl_xor_sync(0xffffffffu, t, 2);
    a0 = (soz ? v2 : v0) + r;
    t = soz ? v1 : v3;  r = __shfl_xor_sync(0xffffffffu, t, 2);
    a1 = (soz ? v3 : v1) + r;
    t = soy ? a0 : a1;  r = __shfl_xor_sync(0xffffffffu, t, 4);
    return (soy ? a1 : a0) + r;
}

__global__ __launch_bounds__(256)
void g2p_split4(const float* __restrict__ pos,
                float* __restrict__ out, int n) {
    int lane = threadIdx.x & 31;
    int warp = (blockIdx.x * blockDim.x + threadIdx.x) >> 5;
    int p = lane >> 3;
    int s = lane & 7;

    int oy = (s >> 2) & 1;
    int oz = (s >> 1) & 1;
    int half = s & 1;
    bool soz = oz != 0, soy = oy != 0;

    int base = warp * 16 + p;
    int i0 = base, i1 = base + 4, i2 = base + 8, i3 = base + 12;
    bool a0 = i0 < n, a1 = i1 < n, a2 = i2 < n, a3 = i3 < n;
    int ic0 = a0 ? i0 : (n - 1), ic1 = a1 ? i1 : (n - 1);
    int ic2 = a2 ? i2 : (n - 1), ic3 = a3 ? i3 : (n - 1);

    PtCtx c0 = g2p_setup(pos, ic0, oy, oz);
    PtCtx c1 = g2p_setup(pos, ic1, oy, oz);
    PtCtx c2 = g2p_setup(pos, ic2, oy, oz);
    PtCtx c3 = g2p_setup(pos, ic3, oy, oz);

    // 8 independent LDG.128
    float4 gA0 = __ldg(&g_grid[2 * c0.nidA + half]);
    float4 gB0 = __ldg(&g_grid[2 * c0.nidB + half]);
    float4 gA1 = __ldg(&g_grid[2 * c1.nidA + half]);
    float4 gB1 = __ldg(&g_grid[2 * c1.nidB + half]);
    float4 gA2 = __ldg(&g_grid[2 * c2.nidA + half]);
    float4 gB2 = __ldg(&g_grid[2 * c2.nidB + half]);
    float4 gA3 = __ldg(&g_grid[2 * c3.nidA + half]);
    float4 gB3 = __ldg(&g_grid[2 * c3.nidB + half]);

    float r0 = g2p_reduce(c0.wA * gA0.x + c0.wB * gB0.x,
                          c0.wA * gA0.y + c0.wB * gB0.y,
                          c0.wA * gA0.z + c0.wB * gB0.z,
                          c0.wA * gA0.w + c0.wB * gB0.w, soz, soy);
    float r1 = g2p_reduce(c1.wA * gA1.x + c1.wB * gB1.x,
                          c1.wA * gA1.y + c1.wB * gB1.y,
                          c1.wA * gA1.z + c1.wB * gB1.z,
                          c1.wA * gA1.w + c1.wB * gB1.w, soz, soy);
    float r2 = g2p_reduce(c2.wA * gA2.x + c2.wB * gB2.x,
                          c2.wA * gA2.y + c2.wB * gB2.y,
                          c2.wA * gA2.z + c2.wB * gB2.z,
                          c2.wA * gA2.w + c2.wB * gB2.w, soz, soy);
    float r3 = g2p_reduce(c3.wA * gA3.x + c3.wB * gB3.x,
                          c3.wA * gA3.y + c3.wB * gB3.y,
                          c3.wA * gA3.z + c3.wB * gB3.z,
                          c3.wA * gA3.w + c3.wB * gB3.w, soz, soy);

    int comp = half * 4 + oz * 2 + oy;
    if (a0) out[8 * (size_t)i0 + comp] = r0;
    if (a1) out[8 * (size_t)i1 + comp] = r1;
    if (a2) out[8 * (size_t)i2 + comp] = r2;
    if (a3) out[8 * (size_t)i3 + comp] = r3;
}

extern "C" void kernel_launch(void* const* d_in, const int* in_sizes, int n_in,
                              void* d_out, int out_size) {
    const float* pos  = (const float*)d_in[0];   // [N,3] f32
    const float* feat = (const float*)d_in[1];   // [N,8] f32
    float* out        = (float*)d_out;           // [N,8] f32
    int n = in_sizes[0] / 3;

    void* gptr = nullptr;
    cudaGetSymbolAddress(&gptr, g_grid);
    cudaMemsetAsync(gptr, 0, (size_t)NCELLS * 2 * sizeof(float4), 0);

    // p2g: 16 lanes/point -> 16 points per 256-thread block
    int pb = (n + 15) / 16;
    p2g_coop<<<pb, 256>>>(pos, (const float4*)feat, n);

    // g2p: 8 lanes/point, 4 pts/thread -> 128 points per 256-thread block
    int gb = (n + 127) / 128;
    g2p_split4<<<gb, 256>>>(pos, (float*)out, n);
}